// round 4
// baseline (speedup 1.0000x reference)
#include <cuda_runtime.h>
#include <cuda_bf16.h>
#include <math.h>
#include <stdint.h>

#define NMAX 100000
#define EMAX 1700000

// Scratch: per-node P (cols 0..63, includes b1) and Q (cols 64..127). 51.2 MB.
__device__ float g_PQ[(size_t)NMAX * 128];
__device__ int2 g_edges[EMAX];  // packed (src, dst) as int32
__device__ int g_is64;

__device__ __forceinline__ uint32_t smem_u32(const void* p) {
    uint32_t a;
    asm("{ .reg .u64 t; cvta.to.shared.u64 t, %1; cvt.u32.u64 %0, t; }"
        : "=r"(a) : "l"(p));
    return a;
}

// m16n8k16 row.col f32 += bf16*bf16
__device__ __forceinline__ void mma16816(float& c0, float& c1, float& c2, float& c3,
                                         uint32_t a0, uint32_t a1, uint32_t a2, uint32_t a3,
                                         uint32_t b0, uint32_t b1) {
    asm volatile(
        "mma.sync.aligned.m16n8k16.row.col.f32.bf16.bf16.f32 "
        "{%0,%1,%2,%3}, {%4,%5,%6,%7}, {%8,%9}, {%0,%1,%2,%3};"
        : "+f"(c0), "+f"(c1), "+f"(c2), "+f"(c3)
        : "r"(a0), "r"(a1), "r"(a2), "r"(a3), "r"(b0), "r"(b1));
}

__device__ __forceinline__ void ldmatrix_x4(uint32_t* r, uint32_t addr) {
    asm volatile(
        "ldmatrix.sync.aligned.m8n8.x4.shared.b16 {%0,%1,%2,%3}, [%4];"
        : "=r"(r[0]), "=r"(r[1]), "=r"(r[2]), "=r"(r[3]) : "r"(addr));
}

// ===========================================================================
// Detect int64 vs int32 edge_index (jax x64-disabled emits int32).
// ===========================================================================
__global__ void detect_kernel(const unsigned int* __restrict__ ei) {
    __shared__ int any;
    if (threadIdx.x == 0) any = 0;
    __syncthreads();
    if (ei[2 * threadIdx.x + 1] != 0u) any = 1;  // benign race
    __syncthreads();
    if (threadIdx.x == 0) g_is64 = (any == 0) ? 1 : 0;
}

__global__ void conv_edges_kernel(const void* __restrict__ eidx, int E) {
    int i = blockIdx.x * blockDim.x + threadIdx.x;
    if (i >= E) return;
    int s, d;
    if (g_is64) {
        const long long* e64 = (const long long*)eidx;
        s = (int)e64[i];
        d = (int)e64[E + i];
    } else {
        const int* e32 = (const int*)eidx;
        s = e32[i];
        d = e32[E + i];
    }
    g_edges[i] = make_int2(s, d);
}

// ===========================================================================
// Node kernel: PQ[n] = [ x@(W1a-W1b)+b1 | x@W1b ],  x = [feat(64) | xyz(3)]
// ===========================================================================
__global__ __launch_bounds__(256) void node_pq_kernel(
    const float* __restrict__ xyz, const float* __restrict__ feat,
    const float* __restrict__ W1, const float* __restrict__ b1, int N) {
    __shared__ float ws[67][128];
    __shared__ float xs[32][68];

    int tid = threadIdx.x;
    for (int i = tid; i < 67 * 128; i += 256) {
        int k = i >> 7, c = i & 127;
        float w1b = W1[(k + 67) * 64 + (c & 63)];
        ws[k][c] = (c < 64) ? (W1[k * 64 + c] - w1b) : w1b;
    }
    int n0 = blockIdx.x * 32;
    for (int i = tid; i < 32 * 67; i += 256) {
        int n = i / 67, k = i - n * 67;
        int gn = n0 + n;
        float v = 0.f;
        if (gn < N) v = (k < 64) ? feat[(size_t)gn * 64 + k]
                                 : xyz[(size_t)gn * 3 + (k - 64)];
        xs[n][k] = v;
    }
    __syncthreads();

    int cg = tid & 31, ng = tid >> 5;
    int c0 = cg * 4, nr = ng * 4;
    float acc[4][4];
#pragma unroll
    for (int i = 0; i < 4; i++)
#pragma unroll
        for (int j = 0; j < 4; j++)
            acc[i][j] = (c0 < 64) ? b1[c0 + j] : 0.f;

#pragma unroll 67
    for (int k = 0; k < 67; k++) {
        float4 w = *(const float4*)&ws[k][c0];
#pragma unroll
        for (int i = 0; i < 4; i++) {
            float xv = xs[nr + i][k];
            acc[i][0] = fmaf(xv, w.x, acc[i][0]);
            acc[i][1] = fmaf(xv, w.y, acc[i][1]);
            acc[i][2] = fmaf(xv, w.z, acc[i][2]);
            acc[i][3] = fmaf(xv, w.w, acc[i][3]);
        }
    }
#pragma unroll
    for (int i = 0; i < 4; i++) {
        int gn = n0 + nr + i;
        if (gn < N) {
            float4 v = make_float4(acc[i][0], acc[i][1], acc[i][2], acc[i][3]);
            *(float4*)&g_PQ[(size_t)gn * 128 + c0] = v;
        }
    }
}

// ===========================================================================
// Init output to -inf bits (vectorized); finalize -inf -> 0
// ===========================================================================
__global__ void init_kernel(uint4* __restrict__ out, int n4) {
    int i = blockIdx.x * blockDim.x + threadIdx.x;
    if (i < n4)
        out[i] = make_uint4(0xff800000u, 0xff800000u, 0xff800000u, 0xff800000u);
}

__global__ void finalize_kernel(uint4* __restrict__ out, int n4) {
    int i = blockIdx.x * blockDim.x + threadIdx.x;
    if (i >= n4) return;
    uint4 v = out[i];
    bool ch = false;
    if (v.x == 0xff800000u) { v.x = 0u; ch = true; }
    if (v.y == 0xff800000u) { v.y = 0u; ch = true; }
    if (v.z == 0xff800000u) { v.z = 0u; ch = true; }
    if (v.w == 0xff800000u) { v.w = 0u; ch = true; }
    if (ch) out[i] = v;
}

// ===========================================================================
// Float atomic max via int/uint ordering trick.
// ===========================================================================
__device__ __forceinline__ void atomic_max_f(float* a, float v) {
    if (v >= 0.f)
        atomicMax((int*)a, __float_as_int(v));
    else
        atomicMin((unsigned int*)a, __float_as_uint(v));
}

// ===========================================================================
// Edge HMMA kernel. Persistent CTAs, 128 threads = 4 fully independent warps.
// Each warp per tile: 32 edges.
//   z[32,64] = relu(P[dst]+Q[src])  (fp32 -> bf16 hi/lo split, staged in SMEM)
//   Y = zh@Wh + zl@Wh + zh@Wl       (mma.sync m16n8k16, fp32 accum, b2 folded
//                                    into the C-fragment initialization)
//   scatter-max Y into out[dst]     (pre-checked atomics; pre-check monotonic-
//                                    safe: stale read => redundant atomic only)
// W2 hi/lo fragments are register-resident (built once from gmem).
// SMEM: per warp 8KB = zhi[32][128B] + zlo[32][128B], XOR-swizzled for
// conflict-free ldmatrix.
// ===========================================================================
__global__ __launch_bounds__(128) void edge_mma_kernel(
    const float* __restrict__ W2, const float* __restrict__ b2,
    float* __restrict__ out, int E) {
    __shared__ char zbuf[4][8192];

    const int lane = threadIdx.x & 31;
    const int wid = threadIdx.x >> 5;

    // ---- build register-resident W2^T fragments (hi/lo bf16 split) ----
    // b frag for m16n8k16: lane holds n = nt*8 + lane/4, k = ks*16 + r*8 +
    // (lane%4)*2 (+1). W2 is [k][n] row-major.
    uint32_t bh[8][4][2], bl[8][4][2];
    {
        const int nn = lane >> 2;
        const int kk = (lane & 3) * 2;
#pragma unroll
        for (int nt = 0; nt < 8; nt++)
#pragma unroll
            for (int ks = 0; ks < 4; ks++)
#pragma unroll
                for (int r = 0; r < 2; r++) {
                    int n = nt * 8 + nn;
                    int k = ks * 16 + r * 8 + kk;
                    float w0 = W2[k * 64 + n];
                    float w1 = W2[(k + 1) * 64 + n];
                    __nv_bfloat162 h = __floats2bfloat162_rn(w0, w1);
                    __nv_bfloat162 l = __floats2bfloat162_rn(
                        w0 - __bfloat162float(h.x), w1 - __bfloat162float(h.y));
                    bh[nt][ks][r] = *(uint32_t*)&h;
                    bl[nt][ks][r] = *(uint32_t*)&l;
                }
    }
    // b2 pairs per n-tile for C-fragment init (cols nt*8+(lane%4)*2, +1)
    float b2x[8], b2y[8];
#pragma unroll
    for (int nt = 0; nt < 8; nt++) {
        int col = nt * 8 + (lane & 3) * 2;
        b2x[nt] = b2[col];
        b2y[nt] = b2[col + 1];
    }

    const uint32_t zh_base = smem_u32(&zbuf[wid][0]);
    const uint32_t zl_base = zh_base + 4096;
    const uint32_t rswz = (uint32_t)(lane & 7) << 4;

    const int T = (E + 31) >> 5;
    const int gw = blockIdx.x * 4 + wid;
    const int nw = gridDim.x * 4;

    for (int t = gw; t < T; t += nw) {
        int e = t * 32 + lane;
        bool valid = (e < E);
        int2 sd = g_edges[valid ? e : 0];
        int mydst = valid ? sd.y : -1;

        const float4* P = (const float4*)(g_PQ + (size_t)sd.y * 128);
        const float4* Q = (const float4*)(g_PQ + (size_t)sd.x * 128 + 64);

        __syncwarp();  // prior tile's ldmatrix reads done before overwrite

        // gather + relu + bf16 hi/lo split -> SMEM row `lane`
        const uint32_t rb = (uint32_t)lane * 128;
#pragma unroll
        for (int j = 0; j < 8; j++) {  // 8 chunks of 8 elems (16B)
            float4 p0 = P[2 * j], p1 = P[2 * j + 1];
            float4 q0 = Q[2 * j], q1 = Q[2 * j + 1];
            float z0 = fmaxf(p0.x + q0.x, 0.f), z1 = fmaxf(p0.y + q0.y, 0.f);
            float z2 = fmaxf(p0.z + q0.z, 0.f), z3 = fmaxf(p0.w + q0.w, 0.f);
            float z4 = fmaxf(p1.x + q1.x, 0.f), z5 = fmaxf(p1.y + q1.y, 0.f);
            float z6 = fmaxf(p1.z + q1.z, 0.f), z7 = fmaxf(p1.w + q1.w, 0.f);
            __nv_bfloat162 h0 = __floats2bfloat162_rn(z0, z1);
            __nv_bfloat162 h1 = __floats2bfloat162_rn(z2, z3);
            __nv_bfloat162 h2 = __floats2bfloat162_rn(z4, z5);
            __nv_bfloat162 h3 = __floats2bfloat162_rn(z6, z7);
            __nv_bfloat162 l0 = __floats2bfloat162_rn(z0 - __bfloat162float(h0.x),
                                                      z1 - __bfloat162float(h0.y));
            __nv_bfloat162 l1 = __floats2bfloat162_rn(z2 - __bfloat162float(h1.x),
                                                      z3 - __bfloat162float(h1.y));
            __nv_bfloat162 l2 = __floats2bfloat162_rn(z4 - __bfloat162float(h2.x),
                                                      z5 - __bfloat162float(h2.y));
            __nv_bfloat162 l3 = __floats2bfloat162_rn(z6 - __bfloat162float(h3.x),
                                                      z7 - __bfloat162float(h3.y));
            uint32_t off = rb + (((uint32_t)j * 16) ^ rswz);
            uint4 hv = make_uint4(*(uint32_t*)&h0, *(uint32_t*)&h1,
                                  *(uint32_t*)&h2, *(uint32_t*)&h3);
            uint4 lv = make_uint4(*(uint32_t*)&l0, *(uint32_t*)&l1,
                                  *(uint32_t*)&l2, *(uint32_t*)&l3);
            asm volatile("st.shared.v4.b32 [%0], {%1,%2,%3,%4};"
                         :: "r"(zh_base + off), "r"(hv.x), "r"(hv.y), "r"(hv.z), "r"(hv.w));
            asm volatile("st.shared.v4.b32 [%0], {%1,%2,%3,%4};"
                         :: "r"(zl_base + off), "r"(lv.x), "r"(lv.y), "r"(lv.z), "r"(lv.w));
        }
        __syncwarp();

        // ldmatrix lane address pieces
        const int m = lane >> 3, rowin = lane & 7;
        const uint32_t lswz = (uint32_t)rowin << 4;

#pragma unroll
        for (int mt = 0; mt < 2; mt++) {
            // A fragments for this m-tile (4 k-steps, hi and lo)
            uint32_t ah[4][4], al[4][4];
            int row = mt * 16 + ((m & 1) << 3) + rowin;
            uint32_t kb_hi = (uint32_t)((m >> 1) << 4);
#pragma unroll
            for (int ks = 0; ks < 4; ks++) {
                uint32_t off = (uint32_t)row * 128 + (((uint32_t)ks * 32 + kb_hi) ^ lswz);
                ldmatrix_x4(ah[ks], zh_base + off);
                ldmatrix_x4(al[ks], zl_base + off);
            }

            int r0 = mt * 16 + (lane >> 2);
            int d0 = __shfl_sync(0xffffffffu, mydst, r0);
            int d1 = __shfl_sync(0xffffffffu, mydst, r0 + 8);

#pragma unroll
            for (int nt = 0; nt < 8; nt++) {
                float c0 = b2x[nt], c1 = b2y[nt], c2 = b2x[nt], c3 = b2y[nt];
#pragma unroll
                for (int ks = 0; ks < 4; ks++)
                    mma16816(c0, c1, c2, c3, ah[ks][0], ah[ks][1], ah[ks][2],
                             ah[ks][3], bh[nt][ks][0], bh[nt][ks][1]);
#pragma unroll
                for (int ks = 0; ks < 4; ks++)
                    mma16816(c0, c1, c2, c3, al[ks][0], al[ks][1], al[ks][2],
                             al[ks][3], bh[nt][ks][0], bh[nt][ks][1]);
#pragma unroll
                for (int ks = 0; ks < 4; ks++)
                    mma16816(c0, c1, c2, c3, ah[ks][0], ah[ks][1], ah[ks][2],
                             ah[ks][3], bl[nt][ks][0], bl[nt][ks][1]);

                // epilogue: rows r0 (c0,c1) and r0+8 (c2,c3), cols col,col+1
                int col = nt * 8 + (lane & 3) * 2;
                if (d0 >= 0) {
                    float* o = out + (size_t)d0 * 64 + col;
                    float2 cur = *(const float2*)o;
                    if (c0 > cur.x) atomic_max_f(o, c0);
                    if (c1 > cur.y) atomic_max_f(o + 1, c1);
                }
                if (d1 >= 0) {
                    float* o = out + (size_t)d1 * 64 + col;
                    float2 cur = *(const float2*)o;
                    if (c2 > cur.x) atomic_max_f(o, c2);
                    if (c3 > cur.y) atomic_max_f(o + 1, c3);
                }
            }
        }
    }
}

// ===========================================================================
// Inputs: [0]=xyz (N*3 f32), [1]=feat (N*64 f32), [2]=edge_index (2*E int),
//         [3]=W1 (134*64 f32), [4]=b1 (64), [5]=W2 (64*64), [6]=b2 (64)
// ===========================================================================
extern "C" void kernel_launch(void* const* d_in, const int* in_sizes, int n_in,
                              void* d_out, int out_size) {
    const float* xyz  = (const float*)d_in[0];
    const float* feat = (const float*)d_in[1];
    const void*  eidx = d_in[2];
    const float* W1   = (const float*)d_in[3];
    const float* b1   = (const float*)d_in[4];
    const float* W2   = (const float*)d_in[5];
    const float* b2   = (const float*)d_in[6];
    float* out = (float*)d_out;

    int N = in_sizes[0] / 3;
    int E = in_sizes[2] / 2;
    int outn = N * 64;
    int n4 = outn / 4;

    detect_kernel<<<1, 1024>>>((const unsigned int*)eidx);
    conv_edges_kernel<<<(E + 255) / 256, 256>>>(eidx, E);
    node_pq_kernel<<<(N + 31) / 32, 256>>>(xyz, feat, W1, b1, N);
    init_kernel<<<(n4 + 255) / 256, 256>>>((uint4*)out, n4);

    int Twarp = (E + 31) >> 5;
    int grid = 2 * 148;  // persistent, ~2 CTAs/SM (register-bound)
    if (grid > (Twarp + 3) / 4) grid = (Twarp + 3) / 4;
    edge_mma_kernel<<<grid, 128>>>(W2, b2, out, E);

    finalize_kernel<<<(n4 + 255) / 256, 256>>>((uint4*)out, n4);
}

// round 5
// speedup vs baseline: 1.6015x; 1.6015x over previous
#include <cuda_runtime.h>
#include <cuda_bf16.h>
#include <math.h>
#include <stdint.h>

#define NMAX 100000
#define EMAX 1700000

// Scratch: per-node P (cols 0..63, includes b1) and Q (cols 64..127). 51.2 MB.
__device__ float g_PQ[(size_t)NMAX * 128];
__device__ int2 g_edges[EMAX];  // packed (src, dst) as int32
__device__ int g_is64;

__device__ __forceinline__ uint32_t smem_u32(const void* p) {
    uint32_t a;
    asm("{ .reg .u64 t; cvta.to.shared.u64 t, %1; cvt.u32.u64 %0, t; }"
        : "=r"(a) : "l"(p));
    return a;
}

// m16n8k16 row.col f32 += bf16*bf16
__device__ __forceinline__ void mma16816(float* c, const uint32_t* a,
                                         const uint32_t* b) {
    asm volatile(
        "mma.sync.aligned.m16n8k16.row.col.f32.bf16.bf16.f32 "
        "{%0,%1,%2,%3}, {%4,%5,%6,%7}, {%8,%9}, {%0,%1,%2,%3};"
        : "+f"(c[0]), "+f"(c[1]), "+f"(c[2]), "+f"(c[3])
        : "r"(a[0]), "r"(a[1]), "r"(a[2]), "r"(a[3]), "r"(b[0]), "r"(b[1]));
}

__device__ __forceinline__ void ldmatrix_x4(uint32_t* r, uint32_t addr) {
    asm volatile(
        "ldmatrix.sync.aligned.m8n8.x4.shared.b16 {%0,%1,%2,%3}, [%4];"
        : "=r"(r[0]), "=r"(r[1]), "=r"(r[2]), "=r"(r[3]) : "r"(addr));
}

// ===========================================================================
// Detect int64 vs int32 edge_index (jax x64-disabled emits int32).
// ===========================================================================
__global__ void detect_kernel(const unsigned int* __restrict__ ei) {
    __shared__ int any;
    if (threadIdx.x == 0) any = 0;
    __syncthreads();
    if (ei[2 * threadIdx.x + 1] != 0u) any = 1;  // benign race
    __syncthreads();
    if (threadIdx.x == 0) g_is64 = (any == 0) ? 1 : 0;
}

__global__ void conv_edges_kernel(const void* __restrict__ eidx, int E) {
    int i = blockIdx.x * blockDim.x + threadIdx.x;
    if (i >= E) return;
    int s, d;
    if (g_is64) {
        const long long* e64 = (const long long*)eidx;
        s = (int)e64[i];
        d = (int)e64[E + i];
    } else {
        const int* e32 = (const int*)eidx;
        s = e32[i];
        d = e32[E + i];
    }
    g_edges[i] = make_int2(s, d);
}

// ===========================================================================
// Node kernel: PQ[n] = [ x@(W1a-W1b)+b1 | x@W1b ],  x = [feat(64) | xyz(3)]
// ===========================================================================
__global__ __launch_bounds__(256) void node_pq_kernel(
    const float* __restrict__ xyz, const float* __restrict__ feat,
    const float* __restrict__ W1, const float* __restrict__ b1, int N) {
    __shared__ float ws[67][128];
    __shared__ float xs[32][68];

    int tid = threadIdx.x;
    for (int i = tid; i < 67 * 128; i += 256) {
        int k = i >> 7, c = i & 127;
        float w1b = W1[(k + 67) * 64 + (c & 63)];
        ws[k][c] = (c < 64) ? (W1[k * 64 + c] - w1b) : w1b;
    }
    int n0 = blockIdx.x * 32;
    for (int i = tid; i < 32 * 67; i += 256) {
        int n = i / 67, k = i - n * 67;
        int gn = n0 + n;
        float v = 0.f;
        if (gn < N) v = (k < 64) ? feat[(size_t)gn * 64 + k]
                                 : xyz[(size_t)gn * 3 + (k - 64)];
        xs[n][k] = v;
    }
    __syncthreads();

    int cg = tid & 31, ng = tid >> 5;
    int c0 = cg * 4, nr = ng * 4;
    float acc[4][4];
#pragma unroll
    for (int i = 0; i < 4; i++)
#pragma unroll
        for (int j = 0; j < 4; j++)
            acc[i][j] = (c0 < 64) ? b1[c0 + j] : 0.f;

#pragma unroll 67
    for (int k = 0; k < 67; k++) {
        float4 w = *(const float4*)&ws[k][c0];
#pragma unroll
        for (int i = 0; i < 4; i++) {
            float xv = xs[nr + i][k];
            acc[i][0] = fmaf(xv, w.x, acc[i][0]);
            acc[i][1] = fmaf(xv, w.y, acc[i][1]);
            acc[i][2] = fmaf(xv, w.z, acc[i][2]);
            acc[i][3] = fmaf(xv, w.w, acc[i][3]);
        }
    }
#pragma unroll
    for (int i = 0; i < 4; i++) {
        int gn = n0 + nr + i;
        if (gn < N) {
            float4 v = make_float4(acc[i][0], acc[i][1], acc[i][2], acc[i][3]);
            *(float4*)&g_PQ[(size_t)gn * 128 + c0] = v;
        }
    }
}

// ===========================================================================
// Init output to -inf bits (vectorized); finalize -inf -> 0
// ===========================================================================
__global__ void init_kernel(uint4* __restrict__ out, int n4) {
    int i = blockIdx.x * blockDim.x + threadIdx.x;
    if (i < n4)
        out[i] = make_uint4(0xff800000u, 0xff800000u, 0xff800000u, 0xff800000u);
}

__global__ void finalize_kernel(uint4* __restrict__ out, int n4) {
    int i = blockIdx.x * blockDim.x + threadIdx.x;
    if (i >= n4) return;
    uint4 v = out[i];
    bool ch = false;
    if (v.x == 0xff800000u) { v.x = 0u; ch = true; }
    if (v.y == 0xff800000u) { v.y = 0u; ch = true; }
    if (v.z == 0xff800000u) { v.z = 0u; ch = true; }
    if (v.w == 0xff800000u) { v.w = 0u; ch = true; }
    if (ch) out[i] = v;
}

// ===========================================================================
// Float atomic max via int/uint ordering trick.
// ===========================================================================
__device__ __forceinline__ void atomic_max_f(float* a, float v) {
    if (v >= 0.f)
        atomicMax((int*)a, __float_as_int(v));
    else
        atomicMin((unsigned int*)a, __float_as_uint(v));
}

// ===========================================================================
// Edge HMMA kernel, v2 (occupancy-first). Persistent CTAs, 128 threads =
// 4 independent warps, 4 CTAs/SM (48KB static smem, <=128 regs).
// Per warp-tile (32 edges):
//   z[32,64] = relu(P[dst]+Q[src])  -> bf16 hi/lo split in SMEM (swizzled)
//   Y = zh@Wh + zl@Wh + zh@Wl       -> mma.sync m16n8k16, fp32 accum,
//                                      b2 folded into C-frag init
//   scatter-max into out[dst]       -> pre-check loads issued BEFORE the
//                                      nt's MMAs (latency hidden by tensor
//                                      work); stale pre-check is monotonic-
//                                      safe (only causes a redundant atomic)
// W2^T hi/lo tiles live in SMEM (built once per CTA); B-frags via ldmatrix.
// ===========================================================================
__global__ __launch_bounds__(128, 4) void edge_mma_kernel(
    const float* __restrict__ W2, const float* __restrict__ b2,
    float* __restrict__ out, int E) {
    __shared__ char zbuf[4][8192];   // per warp: hi 4KB + lo 4KB
    __shared__ char wtile[2][8192];  // W2^T hi, lo (64 rows n x 128B k)

    const int tid = threadIdx.x;
    const int lane = tid & 31;
    const int wid = tid >> 5;

    // ---- build swizzled W2^T hi/lo in SMEM (once per CTA) ----
    for (int i = tid; i < 64 * 64; i += 128) {
        int n = i >> 6, k = i & 63;
        float w = W2[k * 64 + n];
        __nv_bfloat16 h = __float2bfloat16(w);
        __nv_bfloat16 l = __float2bfloat16(w - __bfloat162float(h));
        uint32_t off = (uint32_t)n * 128 + (((uint32_t)(2 * k)) ^ ((uint32_t)(n & 7) << 4));
        *(__nv_bfloat16*)(&wtile[0][off]) = h;
        *(__nv_bfloat16*)(&wtile[1][off]) = l;
    }
    __syncthreads();

    const uint32_t zh_base = smem_u32(&zbuf[wid][0]);
    const uint32_t zl_base = zh_base + 4096;
    const uint32_t wh_base = smem_u32(&wtile[0][0]);
    const uint32_t wl_base = smem_u32(&wtile[1][0]);

    // B-frag ldmatrix lane addressing (covers ks pair per x4)
    const uint32_t brow = lane & 7;
    const uint32_t bswz = brow << 4;
    const uint32_t bpart = (((uint32_t)lane >> 3) & 1) * 16 + (((uint32_t)lane >> 4) & 1) * 32;
    const uint32_t boff0 = brow * 128 + (bpart ^ bswz);        // ks0,ks1
    const uint32_t boff1 = brow * 128 + ((bpart + 64) ^ bswz); // ks2,ks3

    // A-frag ldmatrix lane addressing
    const int am = lane >> 3, rowin = lane & 7;
    const uint32_t lswz = (uint32_t)rowin << 4;
    const uint32_t akb = (uint32_t)((am >> 1) << 4);
    const int arow_in = ((am & 1) << 3) + rowin;

    const uint32_t rswz = (uint32_t)(lane & 7) << 4;  // gather-store swizzle
    const int rsel = lane >> 2;
    const int colb = (lane & 3) * 2;

    const int T = (E + 31) >> 5;
    const int gw = blockIdx.x * 4 + wid;
    const int nw = gridDim.x * 4;

    if (gw >= T) return;

    int t = gw;
    int e0 = t * 32 + lane;
    int2 sd = g_edges[(e0 < E) ? e0 : 0];

    for (; t < T; t += nw) {
        int e = t * 32 + lane;
        bool valid = (e < E);
        int mydst = valid ? sd.y : -1;

        const float4* P = (const float4*)(g_PQ + (size_t)sd.y * 128);
        const float4* Q = (const float4*)(g_PQ + (size_t)sd.x * 128 + 64);

        __syncwarp();  // prior tile's ldmatrix reads done before overwrite

        // ---- gather + relu + bf16 hi/lo split -> SMEM row `lane` ----
        const uint32_t rb = (uint32_t)lane * 128;
#pragma unroll
        for (int j = 0; j < 8; j++) {
            float4 p0 = P[2 * j], p1 = P[2 * j + 1];
            float4 q0 = Q[2 * j], q1 = Q[2 * j + 1];
            float z0 = fmaxf(p0.x + q0.x, 0.f), z1 = fmaxf(p0.y + q0.y, 0.f);
            float z2 = fmaxf(p0.z + q0.z, 0.f), z3 = fmaxf(p0.w + q0.w, 0.f);
            float z4 = fmaxf(p1.x + q1.x, 0.f), z5 = fmaxf(p1.y + q1.y, 0.f);
            float z6 = fmaxf(p1.z + q1.z, 0.f), z7 = fmaxf(p1.w + q1.w, 0.f);
            __nv_bfloat162 h0 = __floats2bfloat162_rn(z0, z1);
            __nv_bfloat162 h1 = __floats2bfloat162_rn(z2, z3);
            __nv_bfloat162 h2 = __floats2bfloat162_rn(z4, z5);
            __nv_bfloat162 h3 = __floats2bfloat162_rn(z6, z7);
            __nv_bfloat162 l0 = __floats2bfloat162_rn(z0 - __bfloat162float(h0.x),
                                                      z1 - __bfloat162float(h0.y));
            __nv_bfloat162 l1 = __floats2bfloat162_rn(z2 - __bfloat162float(h1.x),
                                                      z3 - __bfloat162float(h1.y));
            __nv_bfloat162 l2 = __floats2bfloat162_rn(z4 - __bfloat162float(h2.x),
                                                      z5 - __bfloat162float(h2.y));
            __nv_bfloat162 l3 = __floats2bfloat162_rn(z6 - __bfloat162float(h3.x),
                                                      z7 - __bfloat162float(h3.y));
            uint32_t off = rb + (((uint32_t)j * 16) ^ rswz);
            asm volatile("st.shared.v4.b32 [%0], {%1,%2,%3,%4};"
                         :: "r"(zh_base + off),
                            "r"(*(uint32_t*)&h0), "r"(*(uint32_t*)&h1),
                            "r"(*(uint32_t*)&h2), "r"(*(uint32_t*)&h3));
            asm volatile("st.shared.v4.b32 [%0], {%1,%2,%3,%4};"
                         :: "r"(zl_base + off),
                            "r"(*(uint32_t*)&l0), "r"(*(uint32_t*)&l1),
                            "r"(*(uint32_t*)&l2), "r"(*(uint32_t*)&l3));
        }
        __syncwarp();

        // ---- prefetch next tile's edge record (hides L2 latency) ----
        int tn = t + nw;
        if (tn < T) {
            int en = tn * 32 + lane;
            sd = g_edges[(en < E) ? en : 0];
        }

#pragma unroll
        for (int mt = 0; mt < 2; mt++) {
            // A fragments for this 16-row slice (hi + lo, 4 k-steps)
            uint32_t ah[4][4], al[4][4];
            uint32_t rowb = (uint32_t)(mt * 16 + arow_in) * 128;
#pragma unroll
            for (int ks = 0; ks < 4; ks++) {
                uint32_t off = rowb + (((uint32_t)ks * 32 + akb) ^ lswz);
                ldmatrix_x4(ah[ks], zh_base + off);
                ldmatrix_x4(al[ks], zl_base + off);
            }

            int d0 = __shfl_sync(0xffffffffu, mydst, mt * 16 + rsel);
            int d1 = __shfl_sync(0xffffffffu, mydst, mt * 16 + 8 + rsel);
            const float* pc0 = out + (size_t)(d0 < 0 ? 0 : d0) * 64;
            const float* pc1 = out + (size_t)(d1 < 0 ? 0 : d1) * 64;

#pragma unroll
            for (int nt = 0; nt < 8; nt++) {
                int col = nt * 8 + colb;
                // issue long-latency loads first; MMAs below cover them
                float2 cur0 = *(const float2*)(pc0 + col);
                float2 cur1 = *(const float2*)(pc1 + col);
                float2 b2v = *(const float2*)(b2 + col);

                uint32_t bh[4][2], bl[4][2];
                uint32_t wb = (uint32_t)nt * 1024;
                ldmatrix_x4(&bh[0][0], wh_base + wb + boff0);
                ldmatrix_x4(&bh[2][0], wh_base + wb + boff1);
                ldmatrix_x4(&bl[0][0], wl_base + wb + boff0);
                ldmatrix_x4(&bl[2][0], wl_base + wb + boff1);

                float c[4] = {b2v.x, b2v.y, b2v.x, b2v.y};
#pragma unroll
                for (int ks = 0; ks < 4; ks++) mma16816(c, ah[ks], bh[ks]);
#pragma unroll
                for (int ks = 0; ks < 4; ks++) mma16816(c, al[ks], bh[ks]);
#pragma unroll
                for (int ks = 0; ks < 4; ks++) mma16816(c, ah[ks], bl[ks]);

                if (d0 >= 0) {
                    float* o = out + (size_t)d0 * 64 + col;
                    if (c[0] > cur0.x) atomic_max_f(o, c[0]);
                    if (c[1] > cur0.y) atomic_max_f(o + 1, c[1]);
                }
                if (d1 >= 0) {
                    float* o = out + (size_t)d1 * 64 + col;
                    if (c[2] > cur1.x) atomic_max_f(o, c[2]);
                    if (c[3] > cur1.y) atomic_max_f(o + 1, c[3]);
                }
            }
        }
    }
}

// ===========================================================================
// Inputs: [0]=xyz (N*3 f32), [1]=feat (N*64 f32), [2]=edge_index (2*E int),
//         [3]=W1 (134*64 f32), [4]=b1 (64), [5]=W2 (64*64), [6]=b2 (64)
// ===========================================================================
extern "C" void kernel_launch(void* const* d_in, const int* in_sizes, int n_in,
                              void* d_out, int out_size) {
    const float* xyz  = (const float*)d_in[0];
    const float* feat = (const float*)d_in[1];
    const void*  eidx = d_in[2];
    const float* W1   = (const float*)d_in[3];
    const float* b1   = (const float*)d_in[4];
    const float* W2   = (const float*)d_in[5];
    const float* b2   = (const float*)d_in[6];
    float* out = (float*)d_out;

    int N = in_sizes[0] / 3;
    int E = in_sizes[2] / 2;
    int outn = N * 64;
    int n4 = outn / 4;

    detect_kernel<<<1, 1024>>>((const unsigned int*)eidx);
    conv_edges_kernel<<<(E + 255) / 256, 256>>>(eidx, E);
    node_pq_kernel<<<(N + 31) / 32, 256>>>(xyz, feat, W1, b1, N);
    init_kernel<<<(n4 + 255) / 256, 256>>>((uint4*)out, n4);

    int Twarp = (E + 31) >> 5;
    int grid = 4 * 148;  // persistent, 4 CTAs/SM
    if (grid > (Twarp + 3) / 4) grid = (Twarp + 3) / 4;
    edge_mma_kernel<<<grid, 128>>>(W2, b2, out, E);

    finalize_kernel<<<(n4 + 255) / 256, 256>>>((uint4*)out, n4);
}

// round 6
// speedup vs baseline: 2.0590x; 1.2856x over previous
#include <cuda_runtime.h>
#include <cuda_bf16.h>
#include <math.h>
#include <stdint.h>

#define NMAX 100000
#define EMAX 1700000

// Scratch: per-node P (cols 0..63, includes b1) and Q (cols 64..127). 51.2 MB.
__device__ float g_PQ[(size_t)NMAX * 128];
__device__ int2 g_edges[EMAX];  // packed (src, dst) as int32
__device__ int g_is64;

__device__ __forceinline__ uint32_t smem_u32(const void* p) {
    uint32_t a;
    asm("{ .reg .u64 t; cvta.to.shared.u64 t, %1; cvt.u32.u64 %0, t; }"
        : "=r"(a) : "l"(p));
    return a;
}

// m16n8k16 row.col f32 += bf16*bf16
__device__ __forceinline__ void mma16816(float* c, const uint32_t* a,
                                         const uint32_t* b) {
    asm volatile(
        "mma.sync.aligned.m16n8k16.row.col.f32.bf16.bf16.f32 "
        "{%0,%1,%2,%3}, {%4,%5,%6,%7}, {%8,%9}, {%0,%1,%2,%3};"
        : "+f"(c[0]), "+f"(c[1]), "+f"(c[2]), "+f"(c[3])
        : "r"(a[0]), "r"(a[1]), "r"(a[2]), "r"(a[3]), "r"(b[0]), "r"(b[1]));
}

__device__ __forceinline__ void ldmatrix_x4(uint32_t* r, uint32_t addr) {
    asm volatile(
        "ldmatrix.sync.aligned.m8n8.x4.shared.b16 {%0,%1,%2,%3}, [%4];"
        : "=r"(r[0]), "=r"(r[1]), "=r"(r[2]), "=r"(r[3]) : "r"(addr));
}

// ===========================================================================
// Detect int64 vs int32 edge_index (jax x64-disabled emits int32).
// ===========================================================================
__global__ void detect_kernel(const unsigned int* __restrict__ ei) {
    __shared__ int any;
    if (threadIdx.x == 0) any = 0;
    __syncthreads();
    if (ei[2 * threadIdx.x + 1] != 0u) any = 1;  // benign race
    __syncthreads();
    if (threadIdx.x == 0) g_is64 = (any == 0) ? 1 : 0;
}

__global__ void conv_edges_kernel(const void* __restrict__ eidx, int E) {
    int i = blockIdx.x * blockDim.x + threadIdx.x;
    if (i >= E) return;
    int s, d;
    if (g_is64) {
        const long long* e64 = (const long long*)eidx;
        s = (int)e64[i];
        d = (int)e64[E + i];
    } else {
        const int* e32 = (const int*)eidx;
        s = e32[i];
        d = e32[E + i];
    }
    g_edges[i] = make_int2(s, d);
}

// ===========================================================================
// Node kernel: PQ[n] = [ x@(W1a-W1b)+b1 | x@W1b ],  x = [feat(64) | xyz(3)]
// ===========================================================================
__global__ __launch_bounds__(256) void node_pq_kernel(
    const float* __restrict__ xyz, const float* __restrict__ feat,
    const float* __restrict__ W1, const float* __restrict__ b1, int N) {
    __shared__ float ws[67][128];
    __shared__ float xs[32][68];

    int tid = threadIdx.x;
    for (int i = tid; i < 67 * 128; i += 256) {
        int k = i >> 7, c = i & 127;
        float w1b = W1[(k + 67) * 64 + (c & 63)];
        ws[k][c] = (c < 64) ? (W1[k * 64 + c] - w1b) : w1b;
    }
    int n0 = blockIdx.x * 32;
    for (int i = tid; i < 32 * 67; i += 256) {
        int n = i / 67, k = i - n * 67;
        int gn = n0 + n;
        float v = 0.f;
        if (gn < N) v = (k < 64) ? feat[(size_t)gn * 64 + k]
                                 : xyz[(size_t)gn * 3 + (k - 64)];
        xs[n][k] = v;
    }
    __syncthreads();

    int cg = tid & 31, ng = tid >> 5;
    int c0 = cg * 4, nr = ng * 4;
    float acc[4][4];
#pragma unroll
    for (int i = 0; i < 4; i++)
#pragma unroll
        for (int j = 0; j < 4; j++)
            acc[i][j] = (c0 < 64) ? b1[c0 + j] : 0.f;

#pragma unroll 67
    for (int k = 0; k < 67; k++) {
        float4 w = *(const float4*)&ws[k][c0];
#pragma unroll
        for (int i = 0; i < 4; i++) {
            float xv = xs[nr + i][k];
            acc[i][0] = fmaf(xv, w.x, acc[i][0]);
            acc[i][1] = fmaf(xv, w.y, acc[i][1]);
            acc[i][2] = fmaf(xv, w.z, acc[i][2]);
            acc[i][3] = fmaf(xv, w.w, acc[i][3]);
        }
    }
#pragma unroll
    for (int i = 0; i < 4; i++) {
        int gn = n0 + nr + i;
        if (gn < N) {
            float4 v = make_float4(acc[i][0], acc[i][1], acc[i][2], acc[i][3]);
            *(float4*)&g_PQ[(size_t)gn * 128 + c0] = v;
        }
    }
}

// ===========================================================================
// Init output to -inf bits (vectorized); finalize -inf -> 0
// ===========================================================================
__global__ void init_kernel(uint4* __restrict__ out, int n4) {
    int i = blockIdx.x * blockDim.x + threadIdx.x;
    if (i < n4)
        out[i] = make_uint4(0xff800000u, 0xff800000u, 0xff800000u, 0xff800000u);
}

__global__ void finalize_kernel(uint4* __restrict__ out, int n4) {
    int i = blockIdx.x * blockDim.x + threadIdx.x;
    if (i >= n4) return;
    uint4 v = out[i];
    bool ch = false;
    if (v.x == 0xff800000u) { v.x = 0u; ch = true; }
    if (v.y == 0xff800000u) { v.y = 0u; ch = true; }
    if (v.z == 0xff800000u) { v.z = 0u; ch = true; }
    if (v.w == 0xff800000u) { v.w = 0u; ch = true; }
    if (ch) out[i] = v;
}

// ===========================================================================
// Float atomic max via int/uint ordering trick.
// ===========================================================================
__device__ __forceinline__ void atomic_max_f(float* a, float v) {
    if (v >= 0.f)
        atomicMax((int*)a, __float_as_int(v));
    else
        atomicMin((unsigned int*)a, __float_as_uint(v));
}

// ===========================================================================
// Edge HMMA kernel, v3: cooperative gather. Persistent CTAs, 128 threads =
// 4 independent warps, 4 CTAs/SM.
// Per warp-tile (32 edges):
//   Gather: lanes 0-15 load edge 2g's full 256B P/Q rows cooperatively,
//           lanes 16-31 load edge 2g+1's -> each LDG.128 touches only 4
//           cache lines (vs 32 with per-lane rows): 8x fewer L1tex wavefronts.
//   z = relu(P[dst]+Q[src]) -> bf16 hi/lo split -> swizzled SMEM rows
//   Y = zh@Wh + zl@Wh + zh@Wl  (mma.sync m16n8k16, fp32 accum, b2 in C-init)
//   scatter-max into out[dst] with monotonic-safe pre-checked atomics.
// ===========================================================================
__global__ __launch_bounds__(128, 4) void edge_mma_kernel(
    const float* __restrict__ W2, const float* __restrict__ b2,
    float* __restrict__ out, int E) {
    __shared__ char zbuf[4][8192];   // per warp: hi 4KB + lo 4KB
    __shared__ char wtile[2][8192];  // W2^T hi, lo (64 rows n x 128B k)

    const int tid = threadIdx.x;
    const int lane = tid & 31;
    const int wid = tid >> 5;

    // ---- build swizzled W2^T hi/lo in SMEM (once per CTA) ----
    for (int i = tid; i < 64 * 64; i += 128) {
        int n = i >> 6, k = i & 63;
        float w = W2[k * 64 + n];
        __nv_bfloat16 h = __float2bfloat16(w);
        __nv_bfloat16 l = __float2bfloat16(w - __bfloat162float(h));
        uint32_t off = (uint32_t)n * 128 + (((uint32_t)(2 * k)) ^ ((uint32_t)(n & 7) << 4));
        *(__nv_bfloat16*)(&wtile[0][off]) = h;
        *(__nv_bfloat16*)(&wtile[1][off]) = l;
    }
    __syncthreads();

    const uint32_t zh_base = smem_u32(&zbuf[wid][0]);
    const uint32_t zl_base = zh_base + 4096;
    const uint32_t wh_base = smem_u32(&wtile[0][0]);
    const uint32_t wl_base = smem_u32(&wtile[1][0]);

    // B-frag ldmatrix lane addressing (covers ks pair per x4)
    const uint32_t brow = lane & 7;
    const uint32_t bswz = brow << 4;
    const uint32_t bpart = (((uint32_t)lane >> 3) & 1) * 16 + (((uint32_t)lane >> 4) & 1) * 32;
    const uint32_t boff0 = brow * 128 + (bpart ^ bswz);        // ks0,ks1
    const uint32_t boff1 = brow * 128 + ((bpart + 64) ^ bswz); // ks2,ks3

    // A-frag ldmatrix lane addressing
    const int am = lane >> 3, rowin = lane & 7;
    const uint32_t lswz = (uint32_t)rowin << 4;
    const uint32_t akb = (uint32_t)((am >> 1) << 4);
    const int arow_in = ((am & 1) << 3) + rowin;

    const int rsel = lane >> 2;
    const int colb = (lane & 3) * 2;

    // b2 pairs register-resident
    float2 b2v[8];
#pragma unroll
    for (int nt = 0; nt < 8; nt++)
        b2v[nt] = *(const float2*)(b2 + nt * 8 + colb);

    // cooperative-gather lane pieces
    const int sub = lane >> 4;              // which edge of the pair
    const int cq = lane & 15;               // column quad (4 floats)
    const uint32_t cbyte = (uint32_t)cq * 8;  // byte offset in bf16 row

    const int T = (E + 31) >> 5;
    const int gw = blockIdx.x * 4 + wid;
    const int nw = gridDim.x * 4;

    if (gw >= T) return;

    int t = gw;
    {
        int e0 = t * 32 + lane;
        // prologue load of this warp's edge records
        int2 tmp = g_edges[(e0 < E) ? e0 : 0];
        // fall through into loop with sd = tmp
        int2 sd = tmp;
        for (; t < T; t += nw) {
            int e = t * 32 + lane;
            bool valid = (e < E);
            int mydst = valid ? sd.y : -1;

            __syncwarp();  // prior tile's ldmatrix reads done before overwrite

            // ---- cooperative gather + relu + bf16 split -> SMEM ----
#pragma unroll 4
            for (int g = 0; g < 16; g++) {
                int esel = 2 * g + sub;
                int d = __shfl_sync(0xffffffffu, sd.y, esel);
                int s = __shfl_sync(0xffffffffu, sd.x, esel);
                float4 p = *((const float4*)(g_PQ + (size_t)d * 128) + cq);
                float4 q = *((const float4*)(g_PQ + (size_t)s * 128 + 64) + cq);
                float z0 = fmaxf(p.x + q.x, 0.f), z1 = fmaxf(p.y + q.y, 0.f);
                float z2 = fmaxf(p.z + q.z, 0.f), z3 = fmaxf(p.w + q.w, 0.f);
                __nv_bfloat162 h01 = __floats2bfloat162_rn(z0, z1);
                __nv_bfloat162 h23 = __floats2bfloat162_rn(z2, z3);
                __nv_bfloat162 l01 = __floats2bfloat162_rn(
                    z0 - __bfloat162float(h01.x), z1 - __bfloat162float(h01.y));
                __nv_bfloat162 l23 = __floats2bfloat162_rn(
                    z2 - __bfloat162float(h23.x), z3 - __bfloat162float(h23.y));
                uint32_t row = (uint32_t)(2 * g + sub);
                uint32_t off = row * 128 + (cbyte ^ ((row & 7) << 4));
                asm volatile("st.shared.v2.b32 [%0], {%1,%2};"
                             :: "r"(zh_base + off),
                                "r"(*(uint32_t*)&h01), "r"(*(uint32_t*)&h23));
                asm volatile("st.shared.v2.b32 [%0], {%1,%2};"
                             :: "r"(zl_base + off),
                                "r"(*(uint32_t*)&l01), "r"(*(uint32_t*)&l23));
            }
            __syncwarp();

            // ---- prefetch next tile's edge record (hides L2 latency) ----
            int tn = t + nw;
            if (tn < T) {
                int en = tn * 32 + lane;
                sd = g_edges[(en < E) ? en : 0];
            }

#pragma unroll
            for (int mt = 0; mt < 2; mt++) {
                // A fragments for this 16-row slice (hi + lo, 4 k-steps)
                uint32_t ah[4][4], al[4][4];
                uint32_t rowb = (uint32_t)(mt * 16 + arow_in) * 128;
#pragma unroll
                for (int ks = 0; ks < 4; ks++) {
                    uint32_t off = rowb + (((uint32_t)ks * 32 + akb) ^ lswz);
                    ldmatrix_x4(ah[ks], zh_base + off);
                    ldmatrix_x4(al[ks], zl_base + off);
                }

                int d0 = __shfl_sync(0xffffffffu, mydst, mt * 16 + rsel);
                int d1 = __shfl_sync(0xffffffffu, mydst, mt * 16 + 8 + rsel);
                const float* pc0 = out + (size_t)(d0 < 0 ? 0 : d0) * 64;
                const float* pc1 = out + (size_t)(d1 < 0 ? 0 : d1) * 64;

#pragma unroll
                for (int nt = 0; nt < 8; nt++) {
                    int col = nt * 8 + colb;
                    // issue long-latency loads first; MMAs below cover them
                    float2 cur0 = *(const float2*)(pc0 + col);
                    float2 cur1 = *(const float2*)(pc1 + col);

                    uint32_t bh[4][2], bl[4][2];
                    uint32_t wb = (uint32_t)nt * 1024;
                    ldmatrix_x4(&bh[0][0], wh_base + wb + boff0);
                    ldmatrix_x4(&bh[2][0], wh_base + wb + boff1);
                    ldmatrix_x4(&bl[0][0], wl_base + wb + boff0);
                    ldmatrix_x4(&bl[2][0], wl_base + wb + boff1);

                    float c[4] = {b2v[nt].x, b2v[nt].y, b2v[nt].x, b2v[nt].y};
#pragma unroll
                    for (int ks = 0; ks < 4; ks++) mma16816(c, ah[ks], bh[ks]);
#pragma unroll
                    for (int ks = 0; ks < 4; ks++) mma16816(c, al[ks], bh[ks]);
#pragma unroll
                    for (int ks = 0; ks < 4; ks++) mma16816(c, ah[ks], bl[ks]);

                    if (d0 >= 0) {
                        float* o = out + (size_t)d0 * 64 + col;
                        if (c[0] > cur0.x) atomic_max_f(o, c[0]);
                        if (c[1] > cur0.y) atomic_max_f(o + 1, c[1]);
                    }
                    if (d1 >= 0) {
                        float* o = out + (size_t)d1 * 64 + col;
                        if (c[2] > cur1.x) atomic_max_f(o, c[2]);
                        if (c[3] > cur1.y) atomic_max_f(o + 1, c[3]);
                    }
                }
            }
        }
    }
}

// ===========================================================================
// Inputs: [0]=xyz (N*3 f32), [1]=feat (N*64 f32), [2]=edge_index (2*E int),
//         [3]=W1 (134*64 f32), [4]=b1 (64), [5]=W2 (64*64), [6]=b2 (64)
// ===========================================================================
extern "C" void kernel_launch(void* const* d_in, const int* in_sizes, int n_in,
                              void* d_out, int out_size) {
    const float* xyz  = (const float*)d_in[0];
    const float* feat = (const float*)d_in[1];
    const void*  eidx = d_in[2];
    const float* W1   = (const float*)d_in[3];
    const float* b1   = (const float*)d_in[4];
    const float* W2   = (const float*)d_in[5];
    const float* b2   = (const float*)d_in[6];
    float* out = (float*)d_out;

    int N = in_sizes[0] / 3;
    int E = in_sizes[2] / 2;
    int outn = N * 64;
    int n4 = outn / 4;

    detect_kernel<<<1, 1024>>>((const unsigned int*)eidx);
    conv_edges_kernel<<<(E + 255) / 256, 256>>>(eidx, E);
    node_pq_kernel<<<(N + 31) / 32, 256>>>(xyz, feat, W1, b1, N);
    init_kernel<<<(n4 + 255) / 256, 256>>>((uint4*)out, n4);

    int Twarp = (E + 31) >> 5;
    int grid = 4 * 148;  // persistent, 4 CTAs/SM
    if (grid > (Twarp + 3) / 4) grid = (Twarp + 3) / 4;
    edge_mma_kernel<<<grid, 128>>>(W2, b2, out, E);

    finalize_kernel<<<(n4 + 255) / 256, 256>>>((uint4*)out, n4);
}